// round 15
// baseline (speedup 1.0000x reference)
#include <cuda_runtime.h>
#include <cstdint>

#define NB 32
#define NC 256
#define NHW 3136
#define NHW4 784
#define NG 32
#define EPSV 1e-5f

#define GRID_BLOCKS 740      // 5 * 148, co-resident at 5 blocks/SM
#define TPB 256
#define NPLANES 8192
#define PLANE_BYTES (NHW * 4)   // 12544
#define NBUF 3

__device__ float4 d_coef[NC];            // (gs, gsh, ms, msh) per channel
__device__ float  d_dot[NB];             // alpha dot accumulators (zero-init)
__device__ unsigned int d_batch_done[NB];
__device__ volatile int d_coef_ready;
__device__ unsigned int pool_ctr;
__device__ unsigned int apply_ctr;
__device__ unsigned int finish_ctr;

__global__ __launch_bounds__(TPB, 5)
void fused_kernel(const float* __restrict__ x, float* __restrict__ out,
                  const float* __restrict__ alpha_w,
                  const float* __restrict__ alpha_b,
                  const float* __restrict__ g_w,
                  const float* __restrict__ g_b,
                  const float* __restrict__ g_rm,
                  const float* __restrict__ g_rv,
                  const float* __restrict__ grp_w,
                  const float* __restrict__ grp_b,
                  const float* __restrict__ grp_rm,
                  const float* __restrict__ grp_rv) {
    __shared__ __align__(128) float sbuf[NBUF][NHW];   // 3 x 12.25KB
    __shared__ unsigned int s_grain;
    __shared__ float s_sc, s_sf;

    const int tid  = threadIdx.x;
    const int lane = tid & 31;

    // block 0: build coefficient table, publish behind ready flag
    if (blockIdx.x == 0) {
        const int c = tid;
        const float gs  = g_w[c] * rsqrtf(g_rv[c] + EPSV);
        const float gsh = g_b[c] - g_rm[c] * gs;
        float ms = 0.0f, msh = 0.0f;
        #pragma unroll 8
        for (int g = 0; g < NG; g++) {
            const int idx = g * NC + c;
            const float sg = grp_w[idx] * rsqrtf(grp_rv[idx] + EPSV);
            ms  += sg;
            msh += grp_b[idx] - grp_rm[idx] * sg;
        }
        d_coef[c] = make_float4(gs, gsh, ms * (1.0f / (float)NG),
                                         msh * (1.0f / (float)NG));
        __threadfence();
        __syncthreads();
        if (tid == 0) d_coef_ready = 1;
    }

    if (tid < 128) {
        // ================= PRODUCERS: warps 0-3, pool planes =================
        for (;;) {
            unsigned int pz;
            if (lane == 0) pz = atomicAdd(&pool_ctr, 1u);
            pz = __shfl_sync(0xffffffffu, pz, 0);
            if (pz >= NPLANES) break;

            const float4* __restrict__ xp =
                reinterpret_cast<const float4*>(x) + (size_t)pz * NHW4;
            float s = 0.0f;
            float4 v[6];
            #pragma unroll
            for (int b = 0; b < 4; b++) {            // 4*6*32 = 768
                #pragma unroll
                for (int k = 0; k < 6; k++)
                    v[k] = xp[lane + (b * 6 + k) * 32];
                #pragma unroll
                for (int k = 0; k < 6; k++)
                    s += (v[k].x + v[k].y) + (v[k].z + v[k].w);
            }
            if (lane < 16) {                         // tail 16
                float4 t = xp[768 + lane];
                s += (t.x + t.y) + (t.z + t.w);
            }
            #pragma unroll
            for (int o = 16; o > 0; o >>= 1)
                s += __shfl_down_sync(0xffffffffu, s, o);
            if (lane == 0) {
                const int b = pz >> 8;
                const float p = s * (1.0f / (float)NHW);
                atomicAdd(&d_dot[b], p * alpha_w[pz & 255]);
                __threadfence();                     // release dot before done
                atomicAdd(&d_batch_done[b], 1u);
            }
        }
    } else {
        // ================= CONSUMERS: warps 4-7, apply planes ================
        const int ctid = tid - 128;

        if (tid == 128) {
            while (d_coef_ready == 0) __nanosleep(64);
        }

        int buf = 0;
        for (;;) {
            if (tid == 128) {
                const unsigned int g0 = atomicAdd(&apply_ctr, 1u);
                s_grain = g0;
                if (g0 < NPLANES) {
                    // drain reused buffer (2 stores may stay in flight)
                    asm volatile("cp.async.bulk.wait_group 2;" ::: "memory");
                    const int b = g0 >> 8;
                    while (*(volatile unsigned int*)&d_batch_done[b] < 256u)
                        __nanosleep(32);
                    __threadfence();                 // acquire
                    float dot;
                    asm volatile("ld.global.cg.f32 %0, [%1];"
                                 : "=f"(dot) : "l"(&d_dot[b]));
                    const float4 cf = d_coef[g0 & 255];
                    const float a  = 1.0f / (1.0f + expf(-(dot + alpha_b[0])));
                    const float na = 1.0f - a;
                    s_sc = na * cf.x + a * cf.z;
                    s_sf = na * cf.y + a * cf.w;
                }
            }
            asm volatile("bar.sync 1, 128;" ::: "memory");
            const unsigned int g = s_grain;
            if (g >= NPLANES) break;
            const float sc = s_sc, sf = s_sf;

            const float4* __restrict__ xp =
                reinterpret_cast<const float4*>(x) + (size_t)g * NHW4;
            float4* __restrict__ sb = reinterpret_cast<float4*>(sbuf[buf]);

            float4 v[6];
            #pragma unroll
            for (int k = 0; k < 6; k++)              // 6*128 = 768
                v[k] = xp[ctid + k * 128];
            #pragma unroll
            for (int k = 0; k < 6; k++) {
                float4 r;
                r.x = fmaf(v[k].x, sc, sf);
                r.y = fmaf(v[k].y, sc, sf);
                r.z = fmaf(v[k].z, sc, sf);
                r.w = fmaf(v[k].w, sc, sf);
                sb[ctid + k * 128] = r;
            }
            if (ctid < 16) {                         // tail 784-768 = 16
                float4 t = xp[768 + ctid];
                float4 r;
                r.x = fmaf(t.x, sc, sf);
                r.y = fmaf(t.y, sc, sf);
                r.z = fmaf(t.z, sc, sf);
                r.w = fmaf(t.w, sc, sf);
                sb[768 + ctid] = r;
            }
            asm volatile("bar.sync 1, 128;" ::: "memory");

            if (tid == 128) {
                asm volatile("fence.proxy.async.shared::cta;" ::: "memory");
                uint32_t saddr = (uint32_t)__cvta_generic_to_shared(sbuf[buf]);
                asm volatile(
                    "cp.async.bulk.global.shared::cta.bulk_group [%0], [%1], %2;"
                    :: "l"(out + (size_t)g * NHW), "r"(saddr),
                       "r"((uint32_t)PLANE_BYTES)
                    : "memory");
                asm volatile("cp.async.bulk.commit_group;" ::: "memory");
            }
            buf = (buf + 1 == NBUF) ? 0 : buf + 1;
        }
        if (tid == 128)
            asm volatile("cp.async.bulk.wait_group 0;" ::: "memory");
    }

    // ---- epilogue: last-finishing block resets all globals for replay ----
    __syncthreads();
    if (tid == 0) {
        if (atomicAdd(&finish_ctr, 1u) == GRID_BLOCKS - 1) {
            pool_ctr  = 0;
            apply_ctr = 0;
            #pragma unroll
            for (int i = 0; i < NB; i++) {
                d_batch_done[i] = 0;
                d_dot[i] = 0.0f;
            }
            d_coef_ready = 0;
            __threadfence();
            finish_ctr = 0;
        }
    }
}

extern "C" void kernel_launch(void* const* d_in, const int* in_sizes, int n_in,
                              void* d_out, int out_size) {
    const float* x       = (const float*)d_in[0];
    // d_in[1] = labels (unused)
    const float* alpha_w = (const float*)d_in[2];
    const float* alpha_b = (const float*)d_in[3];
    const float* g_w     = (const float*)d_in[4];
    const float* g_b     = (const float*)d_in[5];
    const float* g_rm    = (const float*)d_in[6];
    const float* g_rv    = (const float*)d_in[7];
    const float* grp_w   = (const float*)d_in[8];
    const float* grp_b   = (const float*)d_in[9];
    const float* grp_rm  = (const float*)d_in[10];
    const float* grp_rv  = (const float*)d_in[11];
    float* out = (float*)d_out;

    fused_kernel<<<GRID_BLOCKS, TPB>>>(x, out,
                                       alpha_w, alpha_b,
                                       g_w, g_b, g_rm, g_rv,
                                       grp_w, grp_b, grp_rm, grp_rv);
}